// round 17
// baseline (speedup 1.0000x reference)
#include <cuda_runtime.h>
#include <cuda_bf16.h>
#include <cstdint>

#define NN   100000   // nodes
#define NE   200000   // hyperedges
#define NNZV 800000   // pins
#define D    128
#define P    32

#define EBLK ((NE + 1023) / 1024)   // 196
#define NBLK ((NN + 1023) / 1024)   // 98
#define NSCAN (EBLK + NBLK)         // 294

#define SOF 68        // smem stride (uint32) for packed bf16x2 full tiles
#define SMEM_BYTES (128 * SOF * 2 * 4)   // WsT + As = 69632 B

// ---------------- scratch ----------------------------------------------------
__device__ float g_efeat[(size_t)NE * D];   // edge means, fp32 (102.4 MB)
__device__ float g_h1[(size_t)NN * D];      // hconv1 out, fp32 (51.2 MB)
__device__ int   g_ecnt[NE];
__device__ int   g_ncnt[NN];
__device__ int2  g_eodc[NE];    // packed {offset, degree}
__device__ int2  g_nodc[NN];
__device__ int   g_ecur[NE];
__device__ int   g_ncur[NN];
__device__ int   g_epins[NNZV];
__device__ int   g_npins[NNZV];
__device__ unsigned long long g_status[NSCAN];   // lookback scan status

// ---------------- phase 1: count pins ----------------------------------------
__global__ void __launch_bounds__(256)
count_kernel(const int* __restrict__ ni, const int* __restrict__ ei) {
    int t = blockIdx.x * blockDim.x + threadIdx.x;
    if (t < NNZV) {
        atomicAdd(&g_ecnt[ei[t]], 1);
        atomicAdd(&g_ncnt[ni[t]], 1);
    }
}

// ---------------- phase 2: single-pass decoupled-lookback scan ---------------
#define FLAG_AGG (1ULL << 62)
#define FLAG_INC (2ULL << 62)
#define VAL_MASK ((1ULL << 62) - 1)

__global__ void __launch_bounds__(256) scan_kernel() {
    const int* cnt; int n; int2* odc; int* curp; int sbase; int bb;
    if (blockIdx.x < EBLK) {
        cnt = g_ecnt; n = NE; odc = g_eodc; curp = g_ecur; sbase = 0;
        bb = blockIdx.x;
    } else {
        cnt = g_ncnt; n = NN; odc = g_nodc; curp = g_ncur; sbase = EBLK;
        bb = blockIdx.x - EBLK;
    }
    __shared__ int sm[256];
    __shared__ int s_prefix;
    int tid = threadIdx.x;
    int base = bb * 1024 + tid * 4;
    int v[4]; int s = 0;
#pragma unroll
    for (int i = 0; i < 4; i++) {
        int idx = base + i;
        v[i] = (idx < n) ? cnt[idx] : 0;
        s += v[i];
    }
    sm[tid] = s; __syncthreads();
    for (int off = 1; off < 256; off <<= 1) {
        int u = (tid >= off) ? sm[tid - off] : 0;
        __syncthreads();
        sm[tid] += u;
        __syncthreads();
    }
    int excl = sm[tid] - s;
    int block_total = sm[255];

    if (tid == 255) {
        if (bb == 0) {
            atomicExch(&g_status[sbase], FLAG_INC | (unsigned long long)block_total);
            s_prefix = 0;
        } else {
            atomicExch(&g_status[sbase + bb], FLAG_AGG | (unsigned long long)block_total);
            long long pref = 0;
            int i = bb - 1;
            while (true) {
                unsigned long long st;
                do {
                    st = atomicAdd(&g_status[sbase + i], 0ULL);
                } while ((st >> 62) == 0);
                pref += (long long)(st & VAL_MASK);
                if ((st >> 62) == 2) break;
                i--;
            }
            atomicExch(&g_status[sbase + bb],
                       FLAG_INC | (unsigned long long)(pref + block_total));
            s_prefix = (int)pref;
        }
    }
    __syncthreads();
    int run = s_prefix + excl;
#pragma unroll
    for (int i = 0; i < 4; i++) {
        int idx = base + i;
        if (idx < n) {
            odc[idx] = make_int2(run, v[i]);
            curp[idx] = run;
        }
        run += v[i];
    }
}

// ---------------- phase 3: bucket fill ---------------------------------------
__global__ void fill_kernel(const int* __restrict__ ni, const int* __restrict__ ei) {
    int t = blockIdx.x * blockDim.x + threadIdx.x;
    if (t < NNZV) {
        int n = ni[t], e = ei[t];
        g_epins[atomicAdd(&g_ecur[e], 1)] = n;
        g_npins[atomicAdd(&g_ncur[n], 1)] = e;
    }
}

// ---------------- helpers -----------------------------------------------------
__device__ __forceinline__ uint32_t packbf(float a, float b) {
    __nv_bfloat162 v = __float22bfloat162_rn(make_float2(a, b));
    return *(uint32_t*)&v;
}

__device__ __forceinline__ void mma_bf16(float* c,
                                         uint32_t a0, uint32_t a1, uint32_t a2, uint32_t a3,
                                         uint32_t b0, uint32_t b1) {
    asm volatile("mma.sync.aligned.m16n8k16.row.col.f32.bf16.bf16.f32 "
                 "{%0,%1,%2,%3}, {%4,%5,%6,%7}, {%8,%9}, {%0,%1,%2,%3};"
                 : "+f"(c[0]), "+f"(c[1]), "+f"(c[2]), "+f"(c[3])
                 : "r"(a0), "r"(a1), "r"(a2), "r"(a3), "r"(b0), "r"(b1));
}

// ---------------- edge gather: fp32 src -> fp32 dst, full warp per row -------
__global__ void __launch_bounds__(256)
seg_mean_gather_f32_kernel(const float* __restrict__ src,
                           float* __restrict__ dst,
                           const int2* __restrict__ odc,
                           const int* __restrict__ pins, int nseg) {
    int w = blockIdx.x * 8 + (threadIdx.x >> 5);
    if (w >= nseg) return;
    int lane = threadIdx.x & 31;
    int2 oc = __ldg(&odc[w]);
    int off = oc.x, deg = oc.y;
    const float4* s4 = (const float4*)src;   // 32 float4 per row
    float4 s0 = make_float4(0.f, 0.f, 0.f, 0.f);
    float4 s1 = make_float4(0.f, 0.f, 0.f, 0.f);
    int k = 0;
    for (; k + 2 <= deg; k += 2) {
        int r0 = __ldg(&pins[off + k]);
        int r1 = __ldg(&pins[off + k + 1]);
        float4 v0 = __ldg(&s4[(size_t)r0 * 32 + lane]);
        float4 v1 = __ldg(&s4[(size_t)r1 * 32 + lane]);
        s0.x += v0.x; s0.y += v0.y; s0.z += v0.z; s0.w += v0.w;
        s1.x += v1.x; s1.y += v1.y; s1.z += v1.z; s1.w += v1.w;
    }
    if (k < deg) {
        int r0 = __ldg(&pins[off + k]);
        float4 v0 = __ldg(&s4[(size_t)r0 * 32 + lane]);
        s0.x += v0.x; s0.y += v0.y; s0.z += v0.z; s0.w += v0.w;
    }
    float sc = 1.0f / (float)(deg > 0 ? deg : 1);
    float4 o = make_float4((s0.x + s1.x) * sc, (s0.y + s1.y) * sc,
                           (s0.z + s1.z) * sc, (s0.w + s1.w) * sc);
    ((float4*)dst)[(size_t)w * 32 + lane] = o;
}

// ---------------- device: gather node means (fp32 efeat) into smem A tile ----
// Warp handles 16 consecutive rows; FULL warp per row, lane owns 4 fp32 cols.
// No shfl, no unpack, no reduce. Epilogue packs to bf16x2 for the mma tile.
__device__ __forceinline__ void gather_rows_to_smem(
    const float* __restrict__ src, uint32_t* As,
    const int2* __restrict__ odc,
    const int* __restrict__ pins, int nseg, int row0) {
    const int warp = threadIdx.x >> 5, lane = threadIdx.x & 31;
    const float4* s4 = (const float4*)src;
    for (int t = 0; t < 16; t++) {
        int rl = warp * 16 + t;
        int seg = row0 + rl;
        float4 a0 = make_float4(0.f, 0.f, 0.f, 0.f);
        float4 a1 = make_float4(0.f, 0.f, 0.f, 0.f);
        int deg = 0;
        if (seg < nseg) {
            int2 oc = __ldg(&odc[seg]);
            int off = oc.x;
            deg = oc.y;
            int k = 0;
            for (; k + 2 <= deg; k += 2) {
                int r0 = __ldg(&pins[off + k]);
                int r1 = __ldg(&pins[off + k + 1]);
                float4 v0 = __ldg(&s4[(size_t)r0 * 32 + lane]);
                float4 v1 = __ldg(&s4[(size_t)r1 * 32 + lane]);
                a0.x += v0.x; a0.y += v0.y; a0.z += v0.z; a0.w += v0.w;
                a1.x += v1.x; a1.y += v1.y; a1.z += v1.z; a1.w += v1.w;
            }
            if (k < deg) {
                int r0 = __ldg(&pins[off + k]);
                float4 v0 = __ldg(&s4[(size_t)r0 * 32 + lane]);
                a0.x += v0.x; a0.y += v0.y; a0.z += v0.z; a0.w += v0.w;
            }
        }
        float sc = 1.0f / (float)(deg > 0 ? deg : 1);
        uint32_t p0 = packbf((a0.x + a1.x) * sc, (a0.y + a1.y) * sc);
        uint32_t p1 = packbf((a0.z + a1.z) * sc, (a0.w + a1.w) * sc);
        // lane owns packed words 2*lane, 2*lane+1 of row rl
        As[rl * SOF + 2 * lane]     = p0;
        As[rl * SOF + 2 * lane + 1] = p1;
    }
}

// ---------------- device: full-tile mma  acc += As(128x128) @ WsT ------------
__device__ __forceinline__ void mma_full(const uint32_t* As, const uint32_t* WsT,
                                         int warp, int lane, float acc[16][4],
                                         int nfrags) {
    const int wr = warp * 16;
    const int q = lane >> 2, p = lane & 3;
#pragma unroll
    for (int nf = 0; nf < 16; nf++)
#pragma unroll
        for (int j = 0; j < 4; j++) if (nf < nfrags) acc[nf][j] = 0.f;
#pragma unroll
    for (int ks = 0; ks < 8; ks++) {
        int kb = ks * 8;
        uint32_t a0 = As[(wr + q) * SOF + kb + p];
        uint32_t a1 = As[(wr + q + 8) * SOF + kb + p];
        uint32_t a2 = As[(wr + q) * SOF + kb + p + 4];
        uint32_t a3 = As[(wr + q + 8) * SOF + kb + p + 4];
#pragma unroll
        for (int nf = 0; nf < 16; nf++) {
            if (nf < nfrags) {
                uint32_t b0 = WsT[(nf * 8 + q) * SOF + kb + p];
                uint32_t b1 = WsT[(nf * 8 + q) * SOF + kb + p + 4];
                mma_bf16(acc[nf], a0, a1, a2, a3, b0, b1);
            }
        }
    }
}

__device__ __forceinline__ void load_w_tile(const float* __restrict__ W, uint32_t* WsT,
                                            int ncols) {
    for (int i = threadIdx.x; i < ncols * 64; i += 256) {
        int kk = i / ncols, n = i % ncols;
        float w0 = __ldg(&W[(2 * kk) * ncols + n]);
        float w1 = __ldg(&W[(2 * kk + 1) * ncols + n]);
        WsT[n * SOF + kk] = packbf(w0, w1);
    }
}

// ---------------- fused: node-gather + GEMM + bias + ReLU -> fp32 ------------
__global__ void __launch_bounds__(256)
ngather_gemm_kernel(const float* __restrict__ efeat,
                    const float* __restrict__ W, const float* __restrict__ b,
                    float* __restrict__ out, int nrows) {
    extern __shared__ uint32_t smu[];
    uint32_t* WsT = smu;
    uint32_t* As  = smu + 128 * SOF;
    const int tid = threadIdx.x;
    const int row0 = blockIdx.x * 128;
    const int warp = tid >> 5, lane = tid & 31;

    load_w_tile(W, WsT, 128);
    gather_rows_to_smem(efeat, As, g_nodc, g_npins, nrows, row0);
    __syncthreads();

    float acc[16][4];
    mma_full(As, WsT, warp, lane, acc, 16);

    const int q = lane >> 2, p = lane & 3;
    int r_lo = row0 + warp * 16 + q;
    int r_hi = r_lo + 8;
#pragma unroll
    for (int nf = 0; nf < 16; nf++) {
        int c = nf * 8 + 2 * p;
        float bx = __ldg(&b[c]), by = __ldg(&b[c + 1]);
        if (r_lo < nrows)
            *(float2*)&out[(size_t)r_lo * 128 + c] =
                make_float2(fmaxf(acc[nf][0] + bx, 0.f), fmaxf(acc[nf][1] + by, 0.f));
        if (r_hi < nrows)
            *(float2*)&out[(size_t)r_hi * 128 + c] =
                make_float2(fmaxf(acc[nf][2] + bx, 0.f), fmaxf(acc[nf][3] + by, 0.f));
    }
}

// ---------------- fused: node-gather + W2 + Wm1 + Wm2 + softmax -> out -------
__global__ void __launch_bounds__(256)
ngather_gemm_mlp_kernel(const float* __restrict__ efeat,
                        const float* __restrict__ W2, const float* __restrict__ b2,
                        const float* __restrict__ Wm1, const float* __restrict__ bm1,
                        const float* __restrict__ Wm2, const float* __restrict__ bm2,
                        float* __restrict__ out, int nrows) {
    extern __shared__ uint32_t smu[];
    uint32_t* WsT = smu;
    uint32_t* As  = smu + 128 * SOF;
    __shared__ float bs2[P];
    const int tid = threadIdx.x;
    const int row0 = blockIdx.x * 128;
    const int warp = tid >> 5, lane = tid & 31;
    const int wr = warp * 16;
    const int q = lane >> 2, p = lane & 3;

    load_w_tile(W2, WsT, 128);
    if (tid < P) bs2[tid] = bm2[tid];
    gather_rows_to_smem(efeat, As, g_nodc, g_npins, nrows, row0);
    __syncthreads();

    float acc[16][4];
    mma_full(As, WsT, warp, lane, acc, 16);
    __syncthreads();
#pragma unroll
    for (int nf = 0; nf < 16; nf++) {
        int c = nf * 8 + 2 * p;
        float bx = __ldg(&b2[c]), by = __ldg(&b2[c + 1]);
        As[(wr + q) * SOF + nf * 4 + p] =
            packbf(fmaxf(acc[nf][0] + bx, 0.f), fmaxf(acc[nf][1] + by, 0.f));
        As[(wr + q + 8) * SOF + nf * 4 + p] =
            packbf(fmaxf(acc[nf][2] + bx, 0.f), fmaxf(acc[nf][3] + by, 0.f));
    }
    load_w_tile(Wm1, WsT, 128);
    __syncthreads();

    mma_full(As, WsT, warp, lane, acc, 16);
    __syncthreads();
#pragma unroll
    for (int nf = 0; nf < 16; nf++) {
        int c = nf * 8 + 2 * p;
        float bx = __ldg(&bm1[c]), by = __ldg(&bm1[c + 1]);
        As[(wr + q) * SOF + nf * 4 + p] =
            packbf(fmaxf(acc[nf][0] + bx, 0.f), fmaxf(acc[nf][1] + by, 0.f));
        As[(wr + q + 8) * SOF + nf * 4 + p] =
            packbf(fmaxf(acc[nf][2] + bx, 0.f), fmaxf(acc[nf][3] + by, 0.f));
    }
    load_w_tile(Wm2, WsT, 32);
    __syncthreads();

    mma_full(As, WsT, warp, lane, acc, 4);

    float vlo[8], vhi[8];
#pragma unroll
    for (int nf = 0; nf < 4; nf++) {
        int c = nf * 8 + 2 * p;
        vlo[nf * 2]     = acc[nf][0] + bs2[c];
        vlo[nf * 2 + 1] = acc[nf][1] + bs2[c + 1];
        vhi[nf * 2]     = acc[nf][2] + bs2[c];
        vhi[nf * 2 + 1] = acc[nf][3] + bs2[c + 1];
    }
    float mlo = vlo[0], mhi = vhi[0];
#pragma unroll
    for (int j = 1; j < 8; j++) { mlo = fmaxf(mlo, vlo[j]); mhi = fmaxf(mhi, vhi[j]); }
    mlo = fmaxf(mlo, __shfl_xor_sync(0xffffffffu, mlo, 1));
    mlo = fmaxf(mlo, __shfl_xor_sync(0xffffffffu, mlo, 2));
    mhi = fmaxf(mhi, __shfl_xor_sync(0xffffffffu, mhi, 1));
    mhi = fmaxf(mhi, __shfl_xor_sync(0xffffffffu, mhi, 2));
    float slo = 0.f, shi = 0.f;
#pragma unroll
    for (int j = 0; j < 8; j++) {
        vlo[j] = __expf(vlo[j] - mlo); slo += vlo[j];
        vhi[j] = __expf(vhi[j] - mhi); shi += vhi[j];
    }
    slo += __shfl_xor_sync(0xffffffffu, slo, 1);
    slo += __shfl_xor_sync(0xffffffffu, slo, 2);
    shi += __shfl_xor_sync(0xffffffffu, shi, 1);
    shi += __shfl_xor_sync(0xffffffffu, shi, 2);
    float rlo = 1.f / slo, rhi = 1.f / shi;

    int r_lo = row0 + wr + q;
    int r_hi = r_lo + 8;
#pragma unroll
    for (int nf = 0; nf < 4; nf++) {
        int c = nf * 8 + 2 * p;
        if (r_lo < nrows)
            *(float2*)&out[(size_t)r_lo * P + c] =
                make_float2(vlo[nf * 2] * rlo, vlo[nf * 2 + 1] * rlo);
        if (r_hi < nrows)
            *(float2*)&out[(size_t)r_hi * P + c] =
                make_float2(vhi[nf * 2] * rhi, vhi[nf * 2 + 1] * rhi);
    }
}

// ---------------- launch ------------------------------------------------------
extern "C" void kernel_launch(void* const* d_in, const int* in_sizes, int n_in,
                              void* d_out, int out_size) {
    const float* x   = (const float*)d_in[0];
    const int*   ni  = (const int*)  d_in[1];
    const int*   ei  = (const int*)  d_in[2];
    const float* W1  = (const float*)d_in[3];
    const float* b1  = (const float*)d_in[4];
    const float* W2  = (const float*)d_in[5];
    const float* b2  = (const float*)d_in[6];
    const float* Wm1 = (const float*)d_in[7];
    const float* bm1 = (const float*)d_in[8];
    const float* Wm2 = (const float*)d_in[9];
    const float* bm2 = (const float*)d_in[10];
    float* out = (float*)d_out;
    (void)in_sizes; (void)n_in; (void)out_size;

    cudaFuncSetAttribute(ngather_gemm_kernel,
                         cudaFuncAttributeMaxDynamicSharedMemorySize, SMEM_BYTES);
    cudaFuncSetAttribute(ngather_gemm_mlp_kernel,
                         cudaFuncAttributeMaxDynamicSharedMemorySize, SMEM_BYTES);

    float* efeat; cudaGetSymbolAddress((void**)&efeat, g_efeat);
    float* h1;   cudaGetSymbolAddress((void**)&h1,    g_h1);
    int* ecnt;   cudaGetSymbolAddress((void**)&ecnt,  g_ecnt);
    int* ncnt;   cudaGetSymbolAddress((void**)&ncnt,  g_ncnt);
    int2* eodc;  cudaGetSymbolAddress((void**)&eodc,  g_eodc);
    int* epins;  cudaGetSymbolAddress((void**)&epins, g_epins);
    void* statusp; cudaGetSymbolAddress(&statusp, g_status);

    // zero via memset nodes (keeps hot kernels at stable ncu kernel indices)
    cudaMemsetAsync(ecnt, 0, NE * sizeof(int));
    cudaMemsetAsync(ncnt, 0, NN * sizeof(int));
    cudaMemsetAsync(statusp, 0, NSCAN * sizeof(unsigned long long));

    // ---- CSR build (kernels 0..2) ----
    count_kernel<<<(NNZV + 255) / 256, 256>>>(ni, ei);   // k0
    scan_kernel<<<NSCAN, 256>>>();                        // k1
    fill_kernel<<<(NNZV + 255) / 256, 256>>>(ni, ei);     // k2

    const int egrid = (NE + 7) / 8;
    const int ggrid = (NN + 127) / 128;

    // ---- hconv layer 1 (kernel 3 = edge gather -> gets profiled) ----
    seg_mean_gather_f32_kernel<<<egrid, 256>>>(x, efeat, eodc, epins, NE);   // k3
    ngather_gemm_kernel<<<ggrid, 256, SMEM_BYTES>>>(efeat, W1, b1, h1, NN);  // k4

    // ---- hconv layer 2 + MLP + softmax ----
    seg_mean_gather_f32_kernel<<<egrid, 256>>>(h1, efeat, eodc, epins, NE);  // k5
    ngather_gemm_mlp_kernel<<<ggrid, 256, SMEM_BYTES>>>(
        efeat, W2, b2, Wm1, bm1, Wm2, bm2, out, NN);                         // k6
}